// round 5
// baseline (speedup 1.0000x reference)
#include <cuda_runtime.h>
#include <cuda_fp16.h>
#include <cstdint>

// ---------------- constants ----------------
constexpr int THREADS = 256;     // 4 pairs of warps; each pair owns 32 edges/tile
constexpr int NPAIR   = 4;

constexpr int LDX  = 200;  // X stride (halfs): 400B
constexpr int LDW  = 136;  // weight stride (halfs): 272B
constexpr int LDRB = 24;   // rbf16 stride (halfs)
constexpr int LDSG = 68;   // sigmoid-exchange stride (halfs)

// byte offsets into dynamic smem
constexpr int B_W1E = 0;                        // [192][136] half  (l1|g1)
constexpr int B_W2E = B_W1E + 192*LDW*2;        // [64][136]        (l2|g2)
constexpr int B_W1N = B_W2E + 64*LDW*2;
constexpr int B_W2N = B_W1N + 192*LDW*2;
constexpr int B_WRB = B_W2N + 64*LDW*2;         // [16][136] (We^T | Wn^T, k=9..15 zero)
constexpr int B_B1E = B_WRB + 16*LDW*2;         // [128] float each
constexpr int B_B2E = B_B1E + 128*4;
constexpr int B_B1N = B_B2E + 128*4;
constexpr int B_B2N = B_B1N + 128*4;
constexpr int B_X   = B_B2N + 128*4;            // 4 x [32][200] half (per pair)
constexpr int B_RB  = B_X  + NPAIR*32*LDX*2;    // 4 x [32][24] half
constexpr int B_SG  = B_RB + NPAIR*32*LDRB*2;   // 4 x [32][68] half
constexpr int SMEM_BYTES = B_SG + NPAIR*32*LDSG*2;   // = 220416

__device__ __forceinline__ float fsig(float x) {
    float t;
    asm("tanh.approx.f32 %0, %1;\n" : "=f"(t) : "f"(x * 0.5f));
    return fmaf(t, 0.5f, 0.5f);
}
__device__ __forceinline__ float fsilu(float x) { return x * fsig(x); }

__device__ __forceinline__ uint32_t cvta_s(const void* p) {
    return (uint32_t)__cvta_generic_to_shared(p);
}
__device__ __forceinline__ void ldx4(uint32_t* r, uint32_t a) {
    asm volatile("ldmatrix.sync.aligned.m8n8.x4.shared.b16 {%0,%1,%2,%3}, [%4];\n"
                 : "=r"(r[0]), "=r"(r[1]), "=r"(r[2]), "=r"(r[3]) : "r"(a));
}
__device__ __forceinline__ void ldx4t(uint32_t* r, uint32_t a) {
    asm volatile("ldmatrix.sync.aligned.m8n8.x4.trans.shared.b16 {%0,%1,%2,%3}, [%4];\n"
                 : "=r"(r[0]), "=r"(r[1]), "=r"(r[2]), "=r"(r[3]) : "r"(a));
}
__device__ __forceinline__ void mma16816(float* c, const uint32_t* a, uint32_t b0, uint32_t b1) {
    asm volatile("mma.sync.aligned.m16n8k16.row.col.f32.f16.f16.f32 "
                 "{%0,%1,%2,%3}, {%4,%5,%6,%7}, {%8,%9}, {%0,%1,%2,%3};\n"
                 : "+f"(c[0]), "+f"(c[1]), "+f"(c[2]), "+f"(c[3])
                 : "r"(a[0]), "r"(a[1]), "r"(a[2]), "r"(a[3]), "r"(b0), "r"(b1));
}
__device__ __forceinline__ uint32_t h2pack(float a, float b) {
    __half2 h = __floats2half2_rn(a, b);
    return *(uint32_t*)&h;
}
__device__ __forceinline__ void st4h(__half* p, float4 v) {
    uint2 u;
    u.x = h2pack(v.x, v.y);
    u.y = h2pack(v.z, v.w);
    *(uint2*)p = u;
}
__device__ __forceinline__ void pbar(int id) {
    asm volatile("bar.sync %0, 64;\n" :: "r"(id) : "memory");
}

// GEMM1 partial: acc[2][8][4] += X[32 x k(KT0*16..KT1*16)] @ W1[., nh*64 + 0..63]
template <int KT0, int KT1>
__device__ __forceinline__ void gemm1_part(const __half* X, const __half* W1, int nh,
                                           float acc[2][8][4], int lane)
{
    uint32_t aB = cvta_s(X + (lane & 15) * LDX + ((lane >> 4) << 3));
    uint32_t bB = cvta_s(W1 + (lane & 15) * LDW + nh * 64 + ((lane >> 4) << 3));
    #pragma unroll
    for (int kt = KT0; kt < KT1; ++kt) {
        uint32_t a0[4], a1[4];
        ldx4(a0, aB + kt * 32);
        ldx4(a1, aB + 16 * LDX * 2 + kt * 32);
        uint32_t bk = bB + kt * 16 * LDW * 2;
        #pragma unroll
        for (int nb2 = 0; nb2 < 4; ++nb2) {
            uint32_t b[4];
            ldx4t(b, bk + nb2 * 32);
            mma16816(acc[0][2*nb2],     a0, b[0], b[1]);
            mma16816(acc[0][2*nb2 + 1], a0, b[2], b[3]);
            mma16816(acc[1][2*nb2],     a1, b[0], b[1]);
            mma16816(acc[1][2*nb2 + 1], a1, b[2], b[3]);
        }
    }
}

// bias + silu + repack GEMM1 C-frags into GEMM2 A-frags (per mt: [4 kb][4 regs])
__device__ __forceinline__ void pack_af(const float acc[2][8][4], const float* b1, int nh,
                                        uint32_t af[2][16], int lane)
{
    const int cp = (lane & 3) << 1;
    #pragma unroll
    for (int mt = 0; mt < 2; ++mt)
        #pragma unroll
        for (int nb = 0; nb < 8; ++nb) {
            int c = nh * 64 + nb * 8 + cp;
            float v0 = fsilu(acc[mt][nb][0] + b1[c]);
            float v1 = fsilu(acc[mt][nb][1] + b1[c + 1]);
            float v2 = fsilu(acc[mt][nb][2] + b1[c]);
            float v3 = fsilu(acc[mt][nb][3] + b1[c + 1]);
            int kb = nb >> 1, odd = nb & 1;
            af[mt][kb*4 + odd*2 + 0] = h2pack(v0, v1);
            af[mt][kb*4 + odd*2 + 1] = h2pack(v2, v3);
        }
}

// GEMM2: acc[2][8][4] = AF[32x64] @ W2[., bh*64 + 0..63]  (raw, no bias)
__device__ __forceinline__ void gemm2(const uint32_t af[2][16], const __half* W2, int bh,
                                      float acc[2][8][4], int lane)
{
    #pragma unroll
    for (int mt = 0; mt < 2; ++mt)
        #pragma unroll
        for (int nb = 0; nb < 8; ++nb)
            #pragma unroll
            for (int j = 0; j < 4; ++j) acc[mt][nb][j] = 0.0f;

    uint32_t bB = cvta_s(W2 + (lane & 15) * LDW + bh * 64 + ((lane >> 4) << 3));
    #pragma unroll
    for (int kt = 0; kt < 4; ++kt) {
        uint32_t bk = bB + kt * 16 * LDW * 2;
        #pragma unroll
        for (int nb2 = 0; nb2 < 4; ++nb2) {
            uint32_t b[4];
            ldx4t(b, bk + nb2 * 32);
            mma16816(acc[0][2*nb2],     af[0] + kt*4, b[0], b[1]);
            mma16816(acc[0][2*nb2 + 1], af[0] + kt*4, b[2], b[3]);
            mma16816(acc[1][2*nb2],     af[1] + kt*4, b[0], b[1]);
            mma16816(acc[1][2*nb2 + 1], af[1] + kt*4, b[2], b[3]);
        }
    }
}

// gates: bias + sigmoid -> fp16 exchange buffer
__device__ __forceinline__ void sig_write(const float acc[2][8][4], const float* b2,
                                          __half* sgbuf, int lane)
{
    const int r0 = lane >> 2, cp = (lane & 3) << 1;
    #pragma unroll
    for (int mt = 0; mt < 2; ++mt)
        #pragma unroll
        for (int nb = 0; nb < 8; ++nb) {
            int c = nb * 8 + cp;
            float s0 = fsig(acc[mt][nb][0] + b2[64 + c]);
            float s1 = fsig(acc[mt][nb][1] + b2[64 + c + 1]);
            float s2 = fsig(acc[mt][nb][2] + b2[64 + c]);
            float s3 = fsig(acc[mt][nb][3] + b2[64 + c + 1]);
            *(uint32_t*)(sgbuf + (mt*16 + r0) * LDSG + c)     = h2pack(s0, s1);
            *(uint32_t*)(sgbuf + (mt*16 + r0 + 8) * LDSG + c) = h2pack(s2, s3);
        }
}

// R = rbf @ W^T  (K=16 zero-padded), path selects We (0) / Wn (1)
__device__ __forceinline__ void rbf_gemm(const __half* RB, const __half* WRB, int path,
                                         float accr[2][8][4], int lane)
{
    #pragma unroll
    for (int mt = 0; mt < 2; ++mt)
        #pragma unroll
        for (int nb = 0; nb < 8; ++nb)
            #pragma unroll
            for (int j = 0; j < 4; ++j) accr[mt][nb][j] = 0.0f;

    uint32_t bR = cvta_s(WRB + (lane & 15) * LDW + path * 64 + ((lane >> 4) << 3));
    uint32_t bf[4][4];
    #pragma unroll
    for (int nb2 = 0; nb2 < 4; ++nb2) ldx4t(bf[nb2], bR + nb2 * 32);
    #pragma unroll
    for (int mt = 0; mt < 2; ++mt) {
        uint32_t a[4];
        ldx4(a, cvta_s(RB + (mt*16 + (lane & 15)) * LDRB + ((lane >> 4) << 3)));
        #pragma unroll
        for (int nb2 = 0; nb2 < 4; ++nb2) {
            mma16816(accr[mt][2*nb2],     a, bf[nb2][0], bf[nb2][1]);
            mma16816(accr[mt][2*nb2 + 1], a, bf[nb2][2], bf[nb2][3]);
        }
    }
}

__global__ void __launch_bounds__(THREADS, 1) m3gnet_fused(
    const float* __restrict__ node_feat, const float* __restrict__ edge_feat,
    const float* __restrict__ rbf, const int* __restrict__ src, const int* __restrict__ dst,
    const float* __restrict__ el1w, const float* __restrict__ el1b,
    const float* __restrict__ el2w, const float* __restrict__ el2b,
    const float* __restrict__ eg1w, const float* __restrict__ eg1b,
    const float* __restrict__ eg2w, const float* __restrict__ eg2b,
    const float* __restrict__ nl1w, const float* __restrict__ nl1b,
    const float* __restrict__ nl2w, const float* __restrict__ nl2b,
    const float* __restrict__ ng1w, const float* __restrict__ ng1b,
    const float* __restrict__ ng2w, const float* __restrict__ ng2b,
    const float* __restrict__ eww, const float* __restrict__ nww,
    float* __restrict__ out_e, float* __restrict__ out_v,
    int E)
{
    extern __shared__ char smem[];
    __half* s_w1e = (__half*)(smem + B_W1E);
    __half* s_w2e = (__half*)(smem + B_W2E);
    __half* s_w1n = (__half*)(smem + B_W1N);
    __half* s_w2n = (__half*)(smem + B_W2N);
    __half* s_wrb = (__half*)(smem + B_WRB);
    float*  s_b1e = (float*)(smem + B_B1E);
    float*  s_b2e = (float*)(smem + B_B2E);
    float*  s_b1n = (float*)(smem + B_B1N);
    float*  s_b2n = (float*)(smem + B_B2N);
    __half* s_x   = (__half*)(smem + B_X);
    __half* s_rb  = (__half*)(smem + B_RB);
    __half* s_sg  = (__half*)(smem + B_SG);

    const int tid = threadIdx.x;

    // one-time zero of rbf tiles (cols 9..23 stay 0 for the K=16 MMA)
    for (int i = tid; i < NPAIR * 32 * LDRB; i += THREADS)
        s_rb[i] = __half(0.0f);

    // one-time weight staging
    for (int i = tid; i < 64 * 192; i += THREADS) {
        int n = i / 192, k = i - n * 192;
        s_w1e[k * LDW + n]      = __float2half(el1w[i]);
        s_w1e[k * LDW + 64 + n] = __float2half(eg1w[i]);
        s_w1n[k * LDW + n]      = __float2half(nl1w[i]);
        s_w1n[k * LDW + 64 + n] = __float2half(ng1w[i]);
    }
    for (int i = tid; i < 64 * 64; i += THREADS) {
        int n = i / 64, k = i - n * 64;
        s_w2e[k * LDW + n]      = __float2half(el2w[i]);
        s_w2e[k * LDW + 64 + n] = __float2half(eg2w[i]);
        s_w2n[k * LDW + n]      = __float2half(nl2w[i]);
        s_w2n[k * LDW + 64 + n] = __float2half(ng2w[i]);
    }
    for (int i = tid; i < 128 * 16; i += THREADS) {
        int c = i >> 4, k = i & 15;
        float v = 0.0f;
        if (k < 9) v = (c < 64) ? eww[c * 9 + k] : nww[(c - 64) * 9 + k];
        s_wrb[k * LDW + c] = __float2half(v);
    }
    if (tid < 64) {
        s_b1e[tid] = el1b[tid]; s_b1e[64 + tid] = eg1b[tid];
        s_b2e[tid] = el2b[tid]; s_b2e[64 + tid] = eg2b[tid];
        s_b1n[tid] = nl1b[tid]; s_b1n[64 + tid] = ng1b[tid];
        s_b2n[tid] = nl2b[tid]; s_b2n[64 + tid] = ng2b[tid];
    }
    __syncthreads();
    // ---- from here on: only per-pair named barriers ----

    const int lane = tid & 31;
    const int warp = tid >> 5;
    const int pair = warp >> 1;
    const int role = warp & 1;          // 0 = "A", 1 = "B"
    const int bid  = 1 + pair;
    __half* xb = s_x  + pair * 32 * LDX;
    __half* rb = s_rb + pair * 32 * LDRB;
    __half* sg = s_sg + pair * 32 * LDSG;
    const int r0 = lane >> 2, cp = (lane & 3) << 1;
    const int ptid = tid & 63;
    const int srow = ptid & 31, sec = ptid >> 5;

    const long npt = ((long)E + 31) >> 5;
    for (long wt = (long)blockIdx.x * NPAIR + pair; wt < npt; wt += (long)gridDim.x * NPAIR) {
        const long ebase = wt << 5;

        // ---- pair stages 32 edges: X = [vi | vj | ef] fp16, rbf fp16 ----
        {
            const long e = ebase + srow;
            const bool v = e < (long)E;
            __half* xr = xb + srow * LDX;
            if (sec == 0) {
                if (v) {
                    const int se = src[e];
                    const float4* vs = (const float4*)(node_feat + (long)se * 64);
                    #pragma unroll
                    for (int j = 0; j < 16; ++j) st4h(xr + j * 4, vs[j]);
                    const float4* ef = (const float4*)(edge_feat + e * 64);
                    #pragma unroll
                    for (int j = 0; j < 8; ++j) st4h(xr + 128 + j * 4, ef[j]);
                    #pragma unroll
                    for (int k = 0; k < 9; ++k)
                        rb[srow * LDRB + k] = __float2half(rbf[e * 9 + k]);
                } else {
                    const uint2 z = {0u, 0u};
                    #pragma unroll
                    for (int j = 0; j < 16; ++j) *(uint2*)(xr + j * 4) = z;
                    #pragma unroll
                    for (int j = 0; j < 8; ++j) *(uint2*)(xr + 128 + j * 4) = z;
                    #pragma unroll
                    for (int k = 0; k < 9; ++k) rb[srow * LDRB + k] = __half(0.0f);
                }
            } else {
                if (v) {
                    const int de = dst[e];
                    const float4* vd = (const float4*)(node_feat + (long)de * 64);
                    #pragma unroll
                    for (int j = 0; j < 16; ++j) st4h(xr + 64 + j * 4, vd[j]);
                    const float4* ef = (const float4*)(edge_feat + e * 64);
                    #pragma unroll
                    for (int j = 8; j < 16; ++j) st4h(xr + 128 + j * 4, ef[j]);
                } else {
                    const uint2 z = {0u, 0u};
                    #pragma unroll
                    for (int j = 0; j < 16; ++j) *(uint2*)(xr + 64 + j * 4) = z;
                    #pragma unroll
                    for (int j = 8; j < 16; ++j) *(uint2*)(xr + 128 + j * 4) = z;
                }
            }
        }
        pbar(bid);   // bar1: tile staged

        if (role == 0) {
            // ========== A: H-branch edge ==========
            float acc1[2][8][4];
            #pragma unroll
            for (int mt = 0; mt < 2; ++mt)
                #pragma unroll
                for (int nb = 0; nb < 8; ++nb)
                    #pragma unroll
                    for (int j = 0; j < 4; ++j) acc1[mt][nb][j] = 0.0f;
            gemm1_part<0, 12>(xb, s_w1e, 0, acc1, lane);
            uint32_t af[2][16];
            pack_af(acc1, s_b1e, 0, af, lane);
            float acc2[2][8][4];
            gemm2(af, s_w2e, 0, acc2, lane);
            pbar(bid);   // bar2: B's sig(g2e) ready

            // ---- edge epilogue ----
            float accr[2][8][4];
            rbf_gemm(rb, s_wrb, 0, accr, lane);
            #pragma unroll
            for (int mt = 0; mt < 2; ++mt) {
                const long e0 = ebase + mt*16 + r0, e1 = e0 + 8;
                const bool v0 = e0 < (long)E, v1 = e1 < (long)E;
                #pragma unroll
                for (int nb = 0; nb < 8; ++nb) {
                    int c = nb * 8 + cp;
                    if (v0) {
                        float h0 = fsilu(acc2[mt][nb][0] + s_b2e[c]);
                        float h1 = fsilu(acc2[mt][nb][1] + s_b2e[c + 1]);
                        uint32_t sgv = *(uint32_t*)(sg + (mt*16 + r0) * LDSG + c);
                        float2 sv = __half22float2(*(__half2*)&sgv);
                        float u0 = h0 * sv.x * accr[mt][nb][0];
                        float u1 = h1 * sv.y * accr[mt][nb][1];
                        float2 ef = *(const float2*)(edge_feat + e0 * 64 + c);
                        float o0 = ef.x + u0, o1 = ef.y + u1;
                        *(float2*)(out_e + e0 * 64 + c) = make_float2(o0, o1);
                        *(uint32_t*)(xb + (mt*16 + r0) * LDX + 128 + c) = h2pack(o0, o1);
                    }
                    if (v1) {
                        float h2v = fsilu(acc2[mt][nb][2] + s_b2e[c]);
                        float h3v = fsilu(acc2[mt][nb][3] + s_b2e[c + 1]);
                        uint32_t sgv = *(uint32_t*)(sg + (mt*16 + r0 + 8) * LDSG + c);
                        float2 sv = __half22float2(*(__half2*)&sgv);
                        float u2 = h2v * sv.x * accr[mt][nb][2];
                        float u3 = h3v * sv.y * accr[mt][nb][3];
                        float2 ef = *(const float2*)(edge_feat + e1 * 64 + c);
                        float o2 = ef.x + u2, o3 = ef.y + u3;
                        *(float2*)(out_e + e1 * 64 + c) = make_float2(o2, o3);
                        *(uint32_t*)(xb + (mt*16 + r0 + 8) * LDX + 128 + c) = h2pack(o2, o3);
                    }
                }
            }
            pbar(bid);   // bar3: e_new patch visible

            // ========== A: G-branch node ==========
            #pragma unroll
            for (int mt = 0; mt < 2; ++mt)
                #pragma unroll
                for (int nb = 0; nb < 8; ++nb)
                    #pragma unroll
                    for (int j = 0; j < 4; ++j) acc1[mt][nb][j] = 0.0f;
            gemm1_part<0, 12>(xb, s_w1n, 1, acc1, lane);
            pack_af(acc1, s_b1n, 1, af, lane);
            gemm2(af, s_w2n, 1, acc2, lane);
            sig_write(acc2, s_b2n, sg, lane);
            pbar(bid);   // bar4: sig(g2n) ready
            pbar(bid);   // bar5: B's node epilogue done (tile complete)
        } else {
            // ========== B: G-branch edge ==========
            float acc1[2][8][4];
            #pragma unroll
            for (int mt = 0; mt < 2; ++mt)
                #pragma unroll
                for (int nb = 0; nb < 8; ++nb)
                    #pragma unroll
                    for (int j = 0; j < 4; ++j) acc1[mt][nb][j] = 0.0f;
            gemm1_part<0, 12>(xb, s_w1e, 1, acc1, lane);
            uint32_t af[2][16];
            pack_af(acc1, s_b1e, 1, af, lane);
            float acc2[2][8][4];
            gemm2(af, s_w2e, 1, acc2, lane);
            sig_write(acc2, s_b2e, sg, lane);
            pbar(bid);   // bar2: sig(g2e) ready

            // ========== B: H-branch node, k=0..127 pre-patch (vi|vj cols) ==========
            #pragma unroll
            for (int mt = 0; mt < 2; ++mt)
                #pragma unroll
                for (int nb = 0; nb < 8; ++nb)
                    #pragma unroll
                    for (int j = 0; j < 4; ++j) acc1[mt][nb][j] = 0.0f;
            gemm1_part<0, 8>(xb, s_w1n, 0, acc1, lane);
            pbar(bid);   // bar3: e_new patch visible
            gemm1_part<8, 12>(xb, s_w1n, 0, acc1, lane);
            pack_af(acc1, s_b1n, 0, af, lane);
            gemm2(af, s_w2n, 0, acc2, lane);
            pbar(bid);   // bar4: A's sig(g2n) ready

            // ---- node epilogue: scatter ----
            float accr[2][8][4];
            rbf_gemm(rb, s_wrb, 1, accr, lane);
            #pragma unroll
            for (int mt = 0; mt < 2; ++mt) {
                const long e0 = ebase + mt*16 + r0, e1 = e0 + 8;
                const bool v0 = e0 < (long)E, v1 = e1 < (long)E;
                const int de0 = v0 ? dst[e0] : 0;
                const int de1 = v1 ? dst[e1] : 0;
                #pragma unroll
                for (int nb = 0; nb < 8; ++nb) {
                    int c = nb * 8 + cp;
                    if (v0) {
                        float h0 = fsilu(acc2[mt][nb][0] + s_b2n[c]);
                        float h1 = fsilu(acc2[mt][nb][1] + s_b2n[c + 1]);
                        uint32_t sgv = *(uint32_t*)(sg + (mt*16 + r0) * LDSG + c);
                        float2 sv = __half22float2(*(__half2*)&sgv);
                        float u0 = h0 * sv.x * accr[mt][nb][0];
                        float u1 = h1 * sv.y * accr[mt][nb][1];
                        asm volatile("red.global.add.v2.f32 [%0], {%1,%2};\n"
                                     :: "l"(out_v + (long)de0 * 64 + c), "f"(u0), "f"(u1)
                                     : "memory");
                    }
                    if (v1) {
                        float h2v = fsilu(acc2[mt][nb][2] + s_b2n[c]);
                        float h3v = fsilu(acc2[mt][nb][3] + s_b2n[c + 1]);
                        uint32_t sgv = *(uint32_t*)(sg + (mt*16 + r0 + 8) * LDSG + c);
                        float2 sv = __half22float2(*(__half2*)&sgv);
                        float u2 = h2v * sv.x * accr[mt][nb][2];
                        float u3 = h3v * sv.y * accr[mt][nb][3];
                        asm volatile("red.global.add.v2.f32 [%0], {%1,%2};\n"
                                     :: "l"(out_v + (long)de1 * 64 + c), "f"(u2), "f"(u3)
                                     : "memory");
                    }
                }
            }
            pbar(bid);   // bar5: tile complete
        }
    }
}

__global__ void copy_v_init(const float* __restrict__ nf, float* __restrict__ outv, int n4)
{
    for (int i = blockIdx.x * blockDim.x + threadIdx.x; i < n4; i += gridDim.x * blockDim.x)
        ((float4*)outv)[i] = ((const float4*)nf)[i];
}

extern "C" void kernel_launch(void* const* d_in, const int* in_sizes, int n_in,
                              void* d_out, int out_size)
{
    const float* node_feat = (const float*)d_in[0];
    const float* edge_feat = (const float*)d_in[1];
    const float* rbf       = (const float*)d_in[2];
    const int*   src       = (const int*)d_in[3];
    const int*   dst       = (const int*)d_in[4];
    const float* el1w = (const float*)d_in[5];  const float* el1b = (const float*)d_in[6];
    const float* el2w = (const float*)d_in[7];  const float* el2b = (const float*)d_in[8];
    const float* eg1w = (const float*)d_in[9];  const float* eg1b = (const float*)d_in[10];
    const float* eg2w = (const float*)d_in[11]; const float* eg2b = (const float*)d_in[12];
    const float* nl1w = (const float*)d_in[13]; const float* nl1b = (const float*)d_in[14];
    const float* nl2w = (const float*)d_in[15]; const float* nl2b = (const float*)d_in[16];
    const float* ng1w = (const float*)d_in[17]; const float* ng1b = (const float*)d_in[18];
    const float* ng2w = (const float*)d_in[19]; const float* ng2b = (const float*)d_in[20];
    const float* eww  = (const float*)d_in[21]; const float* nww  = (const float*)d_in[22];

    const int E = in_sizes[3];
    const int N = in_sizes[0] / 64;
    float* out_e = (float*)d_out;
    float* out_v = out_e + (size_t)E * 64;

    int sms = 148;
    cudaDeviceGetAttribute(&sms, cudaDevAttrMultiProcessorCount, 0);

    cudaFuncSetAttribute(m3gnet_fused, cudaFuncAttributeMaxDynamicSharedMemorySize, SMEM_BYTES);

    copy_v_init<<<sms * 4, 256>>>(node_feat, out_v, N * 16);

    m3gnet_fused<<<sms, THREADS, SMEM_BYTES>>>(
        node_feat, edge_feat, rbf, src, dst,
        el1w, el1b, el2w, el2b, eg1w, eg1b, eg2w, eg2b,
        nl1w, nl1b, nl2w, nl2b, ng1w, ng1b, ng2w, ng2b,
        eww, nww, out_e, out_v, E);
}